// round 4
// baseline (speedup 1.0000x reference)
#include <cuda_runtime.h>
#include <cuda_bf16.h>
#include <cstdint>

#define N_ELEM 8388608   // 32*2048*128
#define N_ITER 32        // 2048 / 64
#define CK     64

// dynamic smem layout (bytes). Each tile row = 128 bf16 = 256B, XOR-swizzled.
#define SQH 0
#define SQL 32768
#define SKV 65536
#define KVS 65536
#define OKH 0
#define OKL 16384
#define OVH 32768
#define OVL 49152
#define SMEM_TOTAL (SKV + 2*KVS)   // 196608 = 192KB

__device__ __align__(1024) uint16_t g_qh[N_ELEM];
__device__ __align__(1024) uint16_t g_ql[N_ELEM];
__device__ __align__(1024) uint16_t g_kh[N_ELEM];
__device__ __align__(1024) uint16_t g_kl[N_ELEM];
__device__ __align__(1024) uint16_t g_vh[N_ELEM];
__device__ __align__(1024) uint16_t g_vl[N_ELEM];

__device__ __forceinline__ uint32_t smem_u32(const void* p) {
    uint32_t a;
    asm("{ .reg .u64 t; cvta.to.shared.u64 t, %1; cvt.u32.u64 %0, t; }" : "=r"(a) : "l"(p));
    return a;
}
__device__ __forceinline__ void cp16(uint32_t dst, const void* src) {
    asm volatile("cp.async.cg.shared.global [%0], [%1], 16;" :: "r"(dst), "l"(src));
}
#define CPASYNC_COMMIT() asm volatile("cp.async.commit_group;" ::: "memory")
#define CPASYNC_WAIT0()  asm volatile("cp.async.wait_group 0;" ::: "memory")

// swizzled smem byte address: rows of 256B (16 x 16B cols), col16 ^= row&7
__device__ __forceinline__ uint32_t SWA(uint32_t base, uint32_t row, uint32_t col16) {
    return base + row * 256 + (((col16) ^ (row & 7)) << 4);
}

__device__ __forceinline__ void ldsm4(uint32_t r[4], uint32_t a) {
    asm volatile("ldmatrix.sync.aligned.m8n8.x4.shared.b16 {%0,%1,%2,%3}, [%4];"
        : "=r"(r[0]), "=r"(r[1]), "=r"(r[2]), "=r"(r[3]) : "r"(a));
}
__device__ __forceinline__ void ldsm4t(uint32_t r[4], uint32_t a) {
    asm volatile("ldmatrix.sync.aligned.m8n8.x4.trans.shared.b16 {%0,%1,%2,%3}, [%4];"
        : "=r"(r[0]), "=r"(r[1]), "=r"(r[2]), "=r"(r[3]) : "r"(a));
}
__device__ __forceinline__ void mma16816(float c[4], const uint32_t a[4], uint32_t b0, uint32_t b1) {
    asm volatile("mma.sync.aligned.m16n8k16.row.col.f32.bf16.bf16.f32 "
        "{%0,%1,%2,%3}, {%4,%5,%6,%7}, {%8,%9}, {%0,%1,%2,%3};"
        : "+f"(c[0]), "+f"(c[1]), "+f"(c[2]), "+f"(c[3])
        : "r"(a[0]), "r"(a[1]), "r"(a[2]), "r"(a[3]), "r"(b0), "r"(b1));
}

__device__ __forceinline__ void hilo_u16(float x, uint16_t& h, uint16_t& l) {
    __nv_bfloat16 hb = __float2bfloat16(x);
    float r = x - __bfloat162float(hb);
    h = __bfloat16_as_ushort(hb);
    l = __bfloat16_as_ushort(__float2bfloat16(r));
}

// elementwise fp32 -> bf16 hi/lo split; which: 0=q,1=k,2=v
__global__ void split_kernel(const float4* __restrict__ src, int which) {
    uint16_t *hi, *lo;
    if (which == 0)      { hi = g_qh; lo = g_ql; }
    else if (which == 1) { hi = g_kh; lo = g_kl; }
    else                 { hi = g_vh; lo = g_vl; }
    int i = blockIdx.x * 256 + threadIdx.x;   // 8192 blocks * 256 thr * 4 elems = N_ELEM
    float4 v = src[i];
    uint16_t h0,l0,h1,l1,h2,l2,h3,l3;
    hilo_u16(v.x,h0,l0); hilo_u16(v.y,h1,l1); hilo_u16(v.z,h2,l2); hilo_u16(v.w,h3,l3);
    reinterpret_cast<uint2*>(hi)[i] = make_uint2((uint32_t)h0|((uint32_t)h1<<16), (uint32_t)h2|((uint32_t)h3<<16));
    reinterpret_cast<uint2*>(lo)[i] = make_uint2((uint32_t)l0|((uint32_t)l1<<16), (uint32_t)l2|((uint32_t)l3<<16));
}

// load one 64-row kv chunk (Kh,Kl,Vh,Vl) into buffer buf
__device__ __forceinline__ void load_kv_chunk(uint32_t sb, int buf, int bh, int ch, int tid) {
    uint32_t base = sb + SKV + (uint32_t)buf * KVS;
    size_t eo = ((size_t)bh * 2048 + (size_t)ch * CK) * 128;   // element offset
    const char* kh = (const char*)(g_kh + eo);
    const char* kl = (const char*)(g_kl + eo);
    const char* vh = (const char*)(g_vh + eo);
    const char* vl = (const char*)(g_vl + eo);
    #pragma unroll
    for (int ii = 0; ii < 4; ii++) {
        int i = tid + ii * 256;
        uint32_t r = (uint32_t)(i >> 4), c = (uint32_t)(i & 15);
        uint32_t dst = SWA(0, r, c);          // offset within tile
        const size_t so = (size_t)r * 256 + c * 16;
        cp16(base + OKH + dst, kh + so);
        cp16(base + OKL + dst, kl + so);
        cp16(base + OVH + dst, vh + so);
        cp16(base + OVL + dst, vl + so);
    }
}

__global__ __launch_bounds__(256, 1) void attn_main(const float* __restrict__ scale_p,
                                                    float* __restrict__ out) {
    extern __shared__ __align__(1024) char smem[];
    uint32_t sb = smem_u32(smem);
    const int tid = threadIdx.x;
    const int warp = tid >> 5, lane = tid & 31;
    const int bh = blockIdx.x >> 4, qt = blockIdx.x & 15;

    // ---- prologue: Q hi/lo tiles (128 rows x 256B) ----
    {
        size_t eo = ((size_t)bh * 2048 + (size_t)qt * 128) * 128;
        const char* qh = (const char*)(g_qh + eo);
        const char* ql = (const char*)(g_ql + eo);
        #pragma unroll
        for (int ii = 0; ii < 8; ii++) {
            int i = tid + ii * 256;
            uint32_t r = (uint32_t)(i >> 4), c = (uint32_t)(i & 15);
            uint32_t dst = SWA(0, r, c);
            const size_t so = (size_t)r * 256 + c * 16;
            cp16(sb + SQH + dst, qh + so);
            cp16(sb + SQL + dst, ql + so);
        }
    }
    load_kv_chunk(sb, 0, bh, 0, tid);
    CPASYNC_COMMIT();

    const float scale = __ldg(scale_p);

    // per-lane ldmatrix row/col components
    const uint32_t rowA = (uint32_t)(16 * warp + (lane & 15));          // Q A-frag row
    const uint32_t colA = (uint32_t)(lane >> 4);                        // + 2*kc
    const uint32_t rowKb = (uint32_t)((lane & 7) + ((lane >> 4) << 3)); // + 16*ng
    const uint32_t colKb = (uint32_t)((lane >> 3) & 1);                 // + 2*kc
    const uint32_t rowVb = (uint32_t)((lane & 7) + (((lane >> 3) & 1) << 3)); // + 16*kc
    const uint32_t colVb = (uint32_t)(lane >> 4);                       // + 2*dg

    float o[16][4];
    #pragma unroll
    for (int j = 0; j < 16; j++) { o[j][0] = o[j][1] = o[j][2] = o[j][3] = 0.f; }

    for (int it = 0; it < N_ITER; ++it) {
        CPASYNC_WAIT0();
        __syncthreads();
        if (it + 1 < N_ITER) { load_kv_chunk(sb, (it + 1) & 1, bh, it + 1, tid); }
        CPASYNC_COMMIT();

        const uint32_t kb = sb + SKV + (uint32_t)(it & 1) * KVS;

        // ---- gemm1: S[16x64] = Qh*Kh' + Qh*Kl' + Ql*Kh' ----
        float s[8][4];
        #pragma unroll
        for (int j = 0; j < 8; j++) { s[j][0] = s[j][1] = s[j][2] = s[j][3] = 0.f; }

        #pragma unroll
        for (int kc = 0; kc < 8; kc++) {
            uint32_t aH[4], aL[4];
            ldsm4(aH, SWA(sb + SQH, rowA, 2 * kc + colA));
            ldsm4(aL, SWA(sb + SQL, rowA, 2 * kc + colA));
            #pragma unroll
            for (int ng = 0; ng < 4; ng++) {
                uint32_t bH[4], bL[4];
                ldsm4(bH, SWA(kb + OKH, 16 * ng + rowKb, 2 * kc + colKb));
                ldsm4(bL, SWA(kb + OKL, 16 * ng + rowKb, 2 * kc + colKb));
                mma16816(s[2*ng],   aH, bH[0], bH[1]);
                mma16816(s[2*ng+1], aH, bH[2], bH[3]);
                mma16816(s[2*ng],   aH, bL[0], bL[1]);
                mma16816(s[2*ng+1], aH, bL[2], bL[3]);
                mma16816(s[2*ng],   aL, bH[0], bH[1]);
                mma16816(s[2*ng+1], aL, bH[2], bH[3]);
            }
        }

        // ---- P = relu(S*scale)^2 (in place) ----
        #pragma unroll
        for (int j = 0; j < 8; j++)
            #pragma unroll
            for (int e = 0; e < 4; e++) {
                float x = fmaxf(s[j][e] * scale, 0.f);
                s[j][e] = x * x;
            }

        // ---- gemm2: O[16x128] += Ph*V + Pl*V  (3-term) ----
        #pragma unroll
        for (int kc = 0; kc < 4; kc++) {
            // build A-frags (hi via truncation, lo = residual) from S tiles 2kc, 2kc+1
            uint32_t ah[4], al[4];
            #pragma unroll
            for (int q = 0; q < 4; q++) {
                const int tile = 2 * kc + (q >> 1);
                const int e0 = (q & 1) * 2;            // c0/c1 or c2/c3
                float p0 = s[tile][e0], p1 = s[tile][e0 + 1];
                uint32_t u0 = __float_as_uint(p0), u1 = __float_as_uint(p1);
                uint32_t h;
                asm("prmt.b32 %0, %1, %2, 0x7632;" : "=r"(h) : "r"(u0), "r"(u1));
                ah[q] = h;
                float l0 = p0 - __uint_as_float(u0 & 0xffff0000u);
                float l1 = p1 - __uint_as_float(u1 & 0xffff0000u);
                uint32_t lp;
                asm("cvt.rn.bf16x2.f32 %0, %1, %2;" : "=r"(lp) : "f"(l1), "f"(l0));
                al[q] = lp;
            }
            // note frag order: a0=(rows0-7,klo)=tile2kc c0c1; a1=(rows8-15,klo)=tile2kc c2c3;
            //                  a2=(rows0-7,khi)=tile2kc+1 c0c1; a3=rows8-15 khi.
            uint32_t aHf[4] = { ah[0], ah[1], ah[2], ah[3] };
            uint32_t aLf[4] = { al[0], al[1], al[2], al[3] };
            #pragma unroll
            for (int dg = 0; dg < 8; dg++) {
                uint32_t bH[4], bL[4];
                ldsm4t(bH, SWA(kb + OVH, 16 * kc + rowVb, 2 * dg + colVb));
                ldsm4t(bL, SWA(kb + OVL, 16 * kc + rowVb, 2 * dg + colVb));
                mma16816(o[2*dg],   aHf, bH[0], bH[1]);
                mma16816(o[2*dg+1], aHf, bH[2], bH[3]);
                mma16816(o[2*dg],   aHf, bL[0], bL[1]);
                mma16816(o[2*dg+1], aHf, bL[2], bL[3]);
                mma16816(o[2*dg],   aLf, bH[0], bH[1]);
                mma16816(o[2*dg+1], aLf, bH[2], bH[3]);
            }
        }
    }

    // ---- writeout ----
    {
        const int g = lane >> 2, t = lane & 3;
        size_t row0 = (size_t)bh * 2048 + (size_t)qt * 128 + 16 * warp + g;
        float* r0 = out + row0 * 128 + 2 * t;
        float* r1 = r0 + 8 * 128;
        #pragma unroll
        for (int j = 0; j < 16; j++) {
            *reinterpret_cast<float2*>(r0 + 8 * j) = make_float2(o[j][0], o[j][1]);
            *reinterpret_cast<float2*>(r1 + 8 * j) = make_float2(o[j][2], o[j][3]);
        }
    }
}

extern "C" void kernel_launch(void* const* d_in, const int* in_sizes, int n_in,
                              void* d_out, int out_size) {
    const float* q     = (const float*)d_in[0];
    const float* k     = (const float*)d_in[1];
    const float* v     = (const float*)d_in[2];
    const float* scale = (const float*)d_in[3];
    float* out = (float*)d_out;

    cudaFuncSetAttribute(attn_main, cudaFuncAttributeMaxDynamicSharedMemorySize, SMEM_TOTAL);

    split_kernel<<<8192, 256>>>((const float4*)q, 0);
    split_kernel<<<8192, 256>>>((const float4*)k, 1);
    split_kernel<<<8192, 256>>>((const float4*)v, 2);
    attn_main<<<512, 256, SMEM_TOTAL>>>(scale, out);
}

// round 6
// speedup vs baseline: 1.3222x; 1.3222x over previous
#include <cuda_runtime.h>
#include <cuda_fp16.h>
#include <cstdint>

#define N_ELEM 8388608   // 32*2048*128
#define N_ITER 32        // 2048 / 64
#define CK     64

// dynamic smem layout (bytes). Tile row = 128 fp16 = 256B, XOR-swizzled.
#define SQH 0
#define SKV 32768
#define KVS 49152
#define OKH 0
#define OKL 16384
#define OVH 32768
#define SMEM_TOTAL (SKV + 2*KVS)   // 131072 = 128KB

__device__ __align__(1024) uint16_t g_qh[N_ELEM];
__device__ __align__(1024) uint16_t g_kh[N_ELEM];
__device__ __align__(1024) uint16_t g_kl[N_ELEM];
__device__ __align__(1024) uint16_t g_vh[N_ELEM];

__device__ __forceinline__ uint32_t smem_u32(const void* p) {
    uint32_t a;
    asm("{ .reg .u64 t; cvta.to.shared.u64 t, %1; cvt.u32.u64 %0, t; }" : "=r"(a) : "l"(p));
    return a;
}
__device__ __forceinline__ void cp16(uint32_t dst, const void* src) {
    asm volatile("cp.async.cg.shared.global [%0], [%1], 16;" :: "r"(dst), "l"(src));
}
#define CPASYNC_COMMIT() asm volatile("cp.async.commit_group;" ::: "memory")
#define CPASYNC_WAIT0()  asm volatile("cp.async.wait_group 0;" ::: "memory")

// swizzled smem byte address: rows of 256B (16 x 16B cols), col16 ^= row&7
__device__ __forceinline__ uint32_t SWA(uint32_t base, uint32_t row, uint32_t col16) {
    return base + row * 256 + (((col16) ^ (row & 7)) << 4);
}

__device__ __forceinline__ void ldsm4(uint32_t r[4], uint32_t a) {
    asm volatile("ldmatrix.sync.aligned.m8n8.x4.shared.b16 {%0,%1,%2,%3}, [%4];"
        : "=r"(r[0]), "=r"(r[1]), "=r"(r[2]), "=r"(r[3]) : "r"(a));
}
__device__ __forceinline__ void ldsm4t(uint32_t r[4], uint32_t a) {
    asm volatile("ldmatrix.sync.aligned.m8n8.x4.trans.shared.b16 {%0,%1,%2,%3}, [%4];"
        : "=r"(r[0]), "=r"(r[1]), "=r"(r[2]), "=r"(r[3]) : "r"(a));
}
__device__ __forceinline__ void mma16816(float c[4], const uint32_t a[4], uint32_t b0, uint32_t b1) {
    asm volatile("mma.sync.aligned.m16n8k16.row.col.f32.f16.f16.f32 "
        "{%0,%1,%2,%3}, {%4,%5,%6,%7}, {%8,%9}, {%0,%1,%2,%3};"
        : "+f"(c[0]), "+f"(c[1]), "+f"(c[2]), "+f"(c[3])
        : "r"(a[0]), "r"(a[1]), "r"(a[2]), "r"(a[3]), "r"(b0), "r"(b1));
}

// which: 0 = q -> g_qh (hi only), 1 = k -> g_kh/g_kl (hi/lo), 2 = v -> g_vh (hi only)
__global__ void cvt_kernel(const float4* __restrict__ src, int which) {
    int i = blockIdx.x * 256 + threadIdx.x;   // 8192 blocks * 256 thr * 4 elems = N_ELEM
    float4 v = src[i];
    __half h0 = __float2half_rn(v.x), h1 = __float2half_rn(v.y);
    __half h2 = __float2half_rn(v.z), h3 = __float2half_rn(v.w);
    uint2 hw = make_uint2(
        (uint32_t)__half_as_ushort(h0) | ((uint32_t)__half_as_ushort(h1) << 16),
        (uint32_t)__half_as_ushort(h2) | ((uint32_t)__half_as_ushort(h3) << 16));
    if (which == 0) {
        reinterpret_cast<uint2*>(g_qh)[i] = hw;
    } else if (which == 2) {
        reinterpret_cast<uint2*>(g_vh)[i] = hw;
    } else {
        reinterpret_cast<uint2*>(g_kh)[i] = hw;
        __half l0 = __float2half_rn(v.x - __half2float(h0));
        __half l1 = __float2half_rn(v.y - __half2float(h1));
        __half l2 = __float2half_rn(v.z - __half2float(h2));
        __half l3 = __float2half_rn(v.w - __half2float(h3));
        reinterpret_cast<uint2*>(g_kl)[i] = make_uint2(
            (uint32_t)__half_as_ushort(l0) | ((uint32_t)__half_as_ushort(l1) << 16),
            (uint32_t)__half_as_ushort(l2) | ((uint32_t)__half_as_ushort(l3) << 16));
    }
}

// load one 64-row kv chunk (Kh,Kl,Vh) into buffer buf
__device__ __forceinline__ void load_kv_chunk(uint32_t sb, int buf, int bh, int ch, int tid) {
    uint32_t base = sb + SKV + (uint32_t)buf * KVS;
    size_t eo = ((size_t)bh * 2048 + (size_t)ch * CK) * 128;
    const char* kh = (const char*)(g_kh + eo);
    const char* kl = (const char*)(g_kl + eo);
    const char* vh = (const char*)(g_vh + eo);
    #pragma unroll
    for (int ii = 0; ii < 4; ii++) {
        int i = tid + ii * 256;
        uint32_t r = (uint32_t)(i >> 4), c = (uint32_t)(i & 15);
        uint32_t dst = SWA(0, r, c);
        const size_t so = (size_t)r * 256 + c * 16;
        cp16(base + OKH + dst, kh + so);
        cp16(base + OKL + dst, kl + so);
        cp16(base + OVH + dst, vh + so);
    }
}

__global__ __launch_bounds__(256, 1) void attn_main(const float* __restrict__ scale_p,
                                                    float* __restrict__ out) {
    extern __shared__ __align__(1024) char smem[];
    uint32_t sb = smem_u32(smem);
    const int tid = threadIdx.x;
    const int warp = tid >> 5, lane = tid & 31;
    const int bh = blockIdx.x >> 4, qt = blockIdx.x & 15;

    // ---- prologue: Q hi tile (128 rows x 256B) ----
    {
        size_t eo = ((size_t)bh * 2048 + (size_t)qt * 128) * 128;
        const char* qh = (const char*)(g_qh + eo);
        #pragma unroll
        for (int ii = 0; ii < 8; ii++) {
            int i = tid + ii * 256;
            uint32_t r = (uint32_t)(i >> 4), c = (uint32_t)(i & 15);
            cp16(sb + SQH + SWA(0, r, c), qh + (size_t)r * 256 + c * 16);
        }
    }
    load_kv_chunk(sb, 0, bh, 0, tid);
    CPASYNC_COMMIT();

    const float scale = __ldg(scale_p);

    const uint32_t rowA  = (uint32_t)(16 * warp + (lane & 15));
    const uint32_t colA  = (uint32_t)(lane >> 4);
    const uint32_t rowKb = (uint32_t)((lane & 7) + ((lane >> 4) << 3));
    const uint32_t colKb = (uint32_t)((lane >> 3) & 1);
    const uint32_t rowVb = (uint32_t)((lane & 7) + (((lane >> 3) & 1) << 3));
    const uint32_t colVb = (uint32_t)(lane >> 4);

    float o[16][4];
    #pragma unroll
    for (int j = 0; j < 16; j++) { o[j][0] = o[j][1] = o[j][2] = o[j][3] = 0.f; }

    for (int it = 0; it < N_ITER; ++it) {
        CPASYNC_WAIT0();
        __syncthreads();
        if (it + 1 < N_ITER) { load_kv_chunk(sb, (it + 1) & 1, bh, it + 1, tid); }
        CPASYNC_COMMIT();

        const uint32_t kb = sb + SKV + (uint32_t)(it & 1) * KVS;

        // ---- gemm1: S[16x64] = Qh*Kh' + Qh*Kl' ----
        float s[8][4];
        #pragma unroll
        for (int j = 0; j < 8; j++) { s[j][0] = s[j][1] = s[j][2] = s[j][3] = 0.f; }

        #pragma unroll
        for (int kc = 0; kc < 8; kc++) {
            uint32_t aH[4];
            ldsm4(aH, SWA(sb + SQH, rowA, 2 * kc + colA));
            #pragma unroll
            for (int ng = 0; ng < 4; ng++) {
                uint32_t bH[4], bL[4];
                ldsm4(bH, SWA(kb + OKH, 16 * ng + rowKb, 2 * kc + colKb));
                ldsm4(bL, SWA(kb + OKL, 16 * ng + rowKb, 2 * kc + colKb));
                mma16816(s[2*ng],   aH, bH[0], bH[1]);
                mma16816(s[2*ng+1], aH, bH[2], bH[3]);
                mma16816(s[2*ng],   aH, bL[0], bL[1]);
                mma16816(s[2*ng+1], aH, bL[2], bL[3]);
            }
        }

        // ---- P = relu(S*scale)^2 (in place, fp32) ----
        #pragma unroll
        for (int j = 0; j < 8; j++)
            #pragma unroll
            for (int e = 0; e < 4; e++) {
                float x = fmaxf(s[j][e] * scale, 0.f);
                s[j][e] = x * x;
            }

        // ---- gemm2: O[16x128] += (Ph + Pl) * Vh  (fp16 split of P) ----
        #pragma unroll
        for (int kc = 0; kc < 4; kc++) {
            uint32_t ah[4], al[4];
            #pragma unroll
            for (int q = 0; q < 4; q++) {
                const int tile = 2 * kc + (q >> 1);
                const int e0 = (q & 1) * 2;
                float p0 = s[tile][e0], p1 = s[tile][e0 + 1];
                __half2 h2 = __floats2half2_rn(p0, p1);          // low=p0, high=p1
                ah[q] = *reinterpret_cast<uint32_t*>(&h2);
                float2 bk = __half22float2(h2);
                __half2 l2 = __floats2half2_rn(p0 - bk.x, p1 - bk.y);
                al[q] = *reinterpret_cast<uint32_t*>(&l2);
            }
            #pragma unroll
            for (int dg = 0; dg < 8; dg++) {
                uint32_t bH[4];
                ldsm4t(bH, SWA(kb + OVH, 16 * kc + rowVb, 2 * dg + colVb));
                mma16816(o[2*dg],   ah, bH[0], bH[1]);
                mma16816(o[2*dg+1], ah, bH[2], bH[3]);
                mma16816(o[2*dg],   al, bH[0], bH[1]);
                mma16816(o[2*dg+1], al, bH[2], bH[3]);
            }
        }
    }

    // ---- writeout ----
    {
        const int g = lane >> 2, t = lane & 3;
        size_t row0 = (size_t)bh * 2048 + (size_t)qt * 128 + 16 * warp + g;
        float* r0 = out + row0 * 128 + 2 * t;
        float* r1 = r0 + 8 * 128;
        #pragma unroll
        for (int j = 0; j < 16; j++) {
            *reinterpret_cast<float2*>(r0 + 8 * j) = make_float2(o[j][0], o[j][1]);
            *reinterpret_cast<float2*>(r1 + 8 * j) = make_float2(o[j][2], o[j][3]);
        }
    }
}

extern "C" void kernel_launch(void* const* d_in, const int* in_sizes, int n_in,
                              void* d_out, int out_size) {
    const float* q     = (const float*)d_in[0];
    const float* k     = (const float*)d_in[1];
    const float* v     = (const float*)d_in[2];
    const float* scale = (const float*)d_in[3];
    float* out = (float*)d_out;

    cudaFuncSetAttribute(attn_main, cudaFuncAttributeMaxDynamicSharedMemorySize, SMEM_TOTAL);

    cvt_kernel<<<8192, 256>>>((const float4*)q, 0);
    cvt_kernel<<<8192, 256>>>((const float4*)k, 1);
    cvt_kernel<<<8192, 256>>>((const float4*)v, 2);
    attn_main<<<512, 256, SMEM_TOTAL>>>(scale, out);
}

// round 7
// speedup vs baseline: 1.3783x; 1.0424x over previous
#include <cuda_runtime.h>
#include <cuda_fp16.h>
#include <cstdint>

#define N_ELEM 8388608   // 32*2048*128
#define N_ITER 32        // 2048 / 64
#define CK     64

// dynamic smem layout (bytes). Tile row = 128 fp16 = 256B, XOR-swizzled.
#define SQH 0
#define SKV 32768
#define KVS 49152
#define OKH 0
#define OKL 16384
#define OVH 32768
#define SMEM_TOTAL (SKV + 2*KVS)   // 131072 = 128KB

__device__ __align__(1024) uint16_t g_qh[N_ELEM];
__device__ __align__(1024) uint16_t g_kh[N_ELEM];
__device__ __align__(1024) uint16_t g_kl[N_ELEM];
__device__ __align__(1024) uint16_t g_vh[N_ELEM];

__device__ __forceinline__ uint32_t smem_u32(const void* p) {
    uint32_t a;
    asm("{ .reg .u64 t; cvta.to.shared.u64 t, %1; cvt.u32.u64 %0, t; }" : "=r"(a) : "l"(p));
    return a;
}
__device__ __forceinline__ void cp16(uint32_t dst, const void* src) {
    asm volatile("cp.async.cg.shared.global [%0], [%1], 16;" :: "r"(dst), "l"(src));
}
#define CPASYNC_COMMIT() asm volatile("cp.async.commit_group;" ::: "memory")
#define CPASYNC_WAIT0()  asm volatile("cp.async.wait_group 0;" ::: "memory")

// swizzled smem byte address: rows of 256B (16 x 16B cols), col16 ^= row&7
__device__ __forceinline__ uint32_t SWA(uint32_t base, uint32_t row, uint32_t col16) {
    return base + row * 256 + (((col16) ^ (row & 7)) << 4);
}

__device__ __forceinline__ void ldsm4(uint32_t r[4], uint32_t a) {
    asm volatile("ldmatrix.sync.aligned.m8n8.x4.shared.b16 {%0,%1,%2,%3}, [%4];"
        : "=r"(r[0]), "=r"(r[1]), "=r"(r[2]), "=r"(r[3]) : "r"(a));
}
__device__ __forceinline__ void ldsm4t(uint32_t r[4], uint32_t a) {
    asm volatile("ldmatrix.sync.aligned.m8n8.x4.trans.shared.b16 {%0,%1,%2,%3}, [%4];"
        : "=r"(r[0]), "=r"(r[1]), "=r"(r[2]), "=r"(r[3]) : "r"(a));
}
__device__ __forceinline__ void mma16816(float c[4], const uint32_t a[4], uint32_t b0, uint32_t b1) {
    asm volatile("mma.sync.aligned.m16n8k16.row.col.f32.f16.f16.f32 "
        "{%0,%1,%2,%3}, {%4,%5,%6,%7}, {%8,%9}, {%0,%1,%2,%3};"
        : "+f"(c[0]), "+f"(c[1]), "+f"(c[2]), "+f"(c[3])
        : "r"(a[0]), "r"(a[1]), "r"(a[2]), "r"(a[3]), "r"(b0), "r"(b1));
}

// which: 0 = q -> g_qh (hi only), 1 = k -> g_kh/g_kl (hi/lo), 2 = v -> g_vh (hi only)
__global__ void cvt_kernel(const float4* __restrict__ src, int which) {
    int i = blockIdx.x * 256 + threadIdx.x;
    float4 v = src[i];
    __half h0 = __float2half_rn(v.x), h1 = __float2half_rn(v.y);
    __half h2 = __float2half_rn(v.z), h3 = __float2half_rn(v.w);
    uint2 hw = make_uint2(
        (uint32_t)__half_as_ushort(h0) | ((uint32_t)__half_as_ushort(h1) << 16),
        (uint32_t)__half_as_ushort(h2) | ((uint32_t)__half_as_ushort(h3) << 16));
    if (which == 0) {
        reinterpret_cast<uint2*>(g_qh)[i] = hw;
    } else if (which == 2) {
        reinterpret_cast<uint2*>(g_vh)[i] = hw;
    } else {
        reinterpret_cast<uint2*>(g_kh)[i] = hw;
        __half l0 = __float2half_rn(v.x - __half2float(h0));
        __half l1 = __float2half_rn(v.y - __half2float(h1));
        __half l2 = __float2half_rn(v.z - __half2float(h2));
        __half l3 = __float2half_rn(v.w - __half2float(h3));
        reinterpret_cast<uint2*>(g_kl)[i] = make_uint2(
            (uint32_t)__half_as_ushort(l0) | ((uint32_t)__half_as_ushort(l1) << 16),
            (uint32_t)__half_as_ushort(l2) | ((uint32_t)__half_as_ushort(l3) << 16));
    }
}

// load one 64-row kv chunk (Kh,Kl,Vh) into buffer buf
__device__ __forceinline__ void load_kv_chunk(uint32_t sb, int buf, int bh, int ch, int tid) {
    uint32_t base = sb + SKV + (uint32_t)buf * KVS;
    size_t eo = ((size_t)bh * 2048 + (size_t)ch * CK) * 128;
    const char* kh = (const char*)(g_kh + eo);
    const char* kl = (const char*)(g_kl + eo);
    const char* vh = (const char*)(g_vh + eo);
    #pragma unroll
    for (int ii = 0; ii < 4; ii++) {
        int i = tid + ii * 256;
        uint32_t r = (uint32_t)(i >> 4), c = (uint32_t)(i & 15);
        uint32_t dst = SWA(0, r, c);
        const size_t so = (size_t)r * 256 + c * 16;
        cp16(base + OKH + dst, kh + so);
        cp16(base + OKL + dst, kl + so);
        cp16(base + OVH + dst, vh + so);
    }
}

__global__ __launch_bounds__(256, 1) void attn_main(const float* __restrict__ scale_p,
                                                    float* __restrict__ out) {
    extern __shared__ __align__(1024) char smem[];
    uint32_t sb = smem_u32(smem);
    const int tid = threadIdx.x;
    const int warp = tid >> 5, lane = tid & 31;
    const int bh = blockIdx.x >> 4, qt = blockIdx.x & 15;

    // ---- prologue: Q hi tile (128 rows x 256B) + chunk 0 ----
    {
        size_t eo = ((size_t)bh * 2048 + (size_t)qt * 128) * 128;
        const char* qh = (const char*)(g_qh + eo);
        #pragma unroll
        for (int ii = 0; ii < 8; ii++) {
            int i = tid + ii * 256;
            uint32_t r = (uint32_t)(i >> 4), c = (uint32_t)(i & 15);
            cp16(sb + SQH + SWA(0, r, c), qh + (size_t)r * 256 + c * 16);
        }
    }
    load_kv_chunk(sb, 0, bh, 0, tid);
    CPASYNC_COMMIT();

    const float scale = __ldg(scale_p);

    const uint32_t rowA  = (uint32_t)(16 * warp + (lane & 15));
    const uint32_t colA  = (uint32_t)(lane >> 4);
    const uint32_t rowKb = (uint32_t)((lane & 7) + ((lane >> 4) << 3));
    const uint32_t colKb = (uint32_t)((lane >> 3) & 1);
    const uint32_t rowVb = (uint32_t)((lane & 7) + (((lane >> 3) & 1) << 3));
    const uint32_t colVb = (uint32_t)(lane >> 4);

    float o[16][4];
    #pragma unroll
    for (int j = 0; j < 16; j++) { o[j][0] = o[j][1] = o[j][2] = o[j][3] = 0.f; }

    // wait for Q + chunk0; preload Q fragments once (iteration-invariant)
    CPASYNC_WAIT0();
    __syncthreads();
    uint32_t qf[8][4];
    #pragma unroll
    for (int kc = 0; kc < 8; kc++)
        ldsm4(qf[kc], SWA(sb + SQH, rowA, 2 * kc + colA));

    for (int it = 0; it < N_ITER; ++it) {
        if (it > 0) {
            CPASYNC_WAIT0();      // wait chunk it
            __syncthreads();      // all warps done with buffer (it+1)&1 from iter it-1
        }
        if (it + 1 < N_ITER) { load_kv_chunk(sb, (it + 1) & 1, bh, it + 1, tid); }
        CPASYNC_COMMIT();

        const uint32_t kb = sb + SKV + (uint32_t)(it & 1) * KVS;

        // ---- gemm1: S[16x64] = Qh*Kh' + Qh*Kl' ----
        float s[8][4];
        #pragma unroll
        for (int j = 0; j < 8; j++) { s[j][0] = s[j][1] = s[j][2] = s[j][3] = 0.f; }

        #pragma unroll
        for (int kc = 0; kc < 8; kc++) {
            uint32_t bH[4][4], bL[4][4];
            #pragma unroll
            for (int ng = 0; ng < 4; ng++) {
                ldsm4(bH[ng], SWA(kb + OKH, 16 * ng + rowKb, 2 * kc + colKb));
                ldsm4(bL[ng], SWA(kb + OKL, 16 * ng + rowKb, 2 * kc + colKb));
            }
            // hi pass: s0..s7, then lo pass: s0..s7  (same-acc reuse distance = 8)
            #pragma unroll
            for (int ng = 0; ng < 4; ng++) {
                mma16816(s[2*ng],   qf[kc], bH[ng][0], bH[ng][1]);
                mma16816(s[2*ng+1], qf[kc], bH[ng][2], bH[ng][3]);
            }
            #pragma unroll
            for (int ng = 0; ng < 4; ng++) {
                mma16816(s[2*ng],   qf[kc], bL[ng][0], bL[ng][1]);
                mma16816(s[2*ng+1], qf[kc], bL[ng][2], bL[ng][3]);
            }
        }

        // ---- P = relu(S*scale)^2 (in place, fp32) ----
        #pragma unroll
        for (int j = 0; j < 8; j++)
            #pragma unroll
            for (int e = 0; e < 4; e++) {
                float x = fmaxf(s[j][e] * scale, 0.f);
                s[j][e] = x * x;
            }

        // ---- gemm2: O[16x128] += (Ph + Pl) * Vh  (fp16 split of P) ----
        #pragma unroll
        for (int kc = 0; kc < 4; kc++) {
            uint32_t vf[8][4];
            #pragma unroll
            for (int dg = 0; dg < 8; dg++)
                ldsm4t(vf[dg], SWA(kb + OVH, 16 * kc + rowVb, 2 * dg + colVb));

            uint32_t ah[4], al[4];
            #pragma unroll
            for (int q = 0; q < 4; q++) {
                const int tile = 2 * kc + (q >> 1);
                const int e0 = (q & 1) * 2;
                float p0 = s[tile][e0], p1 = s[tile][e0 + 1];
                __half2 h2 = __floats2half2_rn(p0, p1);
                ah[q] = *reinterpret_cast<uint32_t*>(&h2);
                float2 bk = __half22float2(h2);
                __half2 l2 = __floats2half2_rn(p0 - bk.x, p1 - bk.y);
                al[q] = *reinterpret_cast<uint32_t*>(&l2);
            }
            // hi pass o0..o15, then lo pass (same-acc reuse distance = 16)
            #pragma unroll
            for (int dg = 0; dg < 8; dg++) {
                mma16816(o[2*dg],   ah, vf[dg][0], vf[dg][1]);
                mma16816(o[2*dg+1], ah, vf[dg][2], vf[dg][3]);
            }
            #pragma unroll
            for (int dg = 0; dg < 8; dg++) {
                mma16816(o[2*dg],   al, vf[dg][0], vf[dg][1]);
                mma16816(o[2*dg+1], al, vf[dg][2], vf[dg][3]);
            }
        }
    }

    // ---- writeout ----
    {
        const int g = lane >> 2, t = lane & 3;
        size_t row0 = (size_t)bh * 2048 + (size_t)qt * 128 + 16 * warp + g;
        float* r0 = out + row0 * 128 + 2 * t;
        float* r1 = r0 + 8 * 128;
        #pragma unroll
        for (int j = 0; j < 16; j++) {
            *reinterpret_cast<float2*>(r0 + 8 * j) = make_float2(o[j][0], o[j][1]);
            *reinterpret_cast<float2*>(r1 + 8 * j) = make_float2(o[j][2], o[j][3]);
        }
    }
}

extern "C" void kernel_launch(void* const* d_in, const int* in_sizes, int n_in,
                              void* d_out, int out_size) {
    const float* q     = (const float*)d_in[0];
    const float* k     = (const float*)d_in[1];
    const float* v     = (const float*)d_in[2];
    const float* scale = (const float*)d_in[3];
    float* out = (float*)d_out;

    cudaFuncSetAttribute(attn_main, cudaFuncAttributeMaxDynamicSharedMemorySize, SMEM_TOTAL);

    cvt_kernel<<<8192, 256>>>((const float4*)q, 0);
    cvt_kernel<<<8192, 256>>>((const float4*)k, 1);
    cvt_kernel<<<8192, 256>>>((const float4*)v, 2);
    attn_main<<<512, 256, SMEM_TOTAL>>>(scale, out);
}

// round 9
// speedup vs baseline: 1.7078x; 1.2391x over previous
#include <cuda_runtime.h>
#include <cuda_fp16.h>
#include <cstdint>

#define N_ELEM 8388608   // 32*2048*128
#define N_ITER 32        // 2048 / 64
#define CK     64

// dynamic smem layout (bytes). Tile row = 128 fp16 = 256B, XOR-swizzled.
#define SQH 0
#define SKV 32768
#define KVS 49152
#define OKH 0
#define OKL 16384
#define OVH 32768
#define SMEM_TOTAL (SKV + 2*KVS)   // 131072 = 128KB

__device__ __align__(1024) uint16_t g_qh[N_ELEM];
__device__ __align__(1024) uint16_t g_kh[N_ELEM];
__device__ __align__(1024) uint16_t g_kl[N_ELEM];
__device__ __align__(1024) uint16_t g_vh[N_ELEM];

__device__ __forceinline__ uint32_t smem_u32(const void* p) {
    uint32_t a;
    asm("{ .reg .u64 t; cvta.to.shared.u64 t, %1; cvt.u32.u64 %0, t; }" : "=r"(a) : "l"(p));
    return a;
}
__device__ __forceinline__ void cp16(uint32_t dst, const void* src) {
    asm volatile("cp.async.cg.shared.global [%0], [%1], 16;" :: "r"(dst), "l"(src));
}
#define CPASYNC_COMMIT() asm volatile("cp.async.commit_group;" ::: "memory")
#define CPASYNC_WAIT0()  asm volatile("cp.async.wait_group 0;" ::: "memory")

// swizzled smem byte address: rows of 256B (16 x 16B cols), col16 ^= row&7
__device__ __forceinline__ uint32_t SWA(uint32_t base, uint32_t row, uint32_t col16) {
    return base + row * 256 + (((col16) ^ (row & 7)) << 4);
}

__device__ __forceinline__ void ldsm4(uint32_t r[4], uint32_t a) {
    asm volatile("ldmatrix.sync.aligned.m8n8.x4.shared.b16 {%0,%1,%2,%3}, [%4];"
        : "=r"(r[0]), "=r"(r[1]), "=r"(r[2]), "=r"(r[3]) : "r"(a));
}
__device__ __forceinline__ void ldsm4t(uint32_t r[4], uint32_t a) {
    asm volatile("ldmatrix.sync.aligned.m8n8.x4.trans.shared.b16 {%0,%1,%2,%3}, [%4];"
        : "=r"(r[0]), "=r"(r[1]), "=r"(r[2]), "=r"(r[3]) : "r"(a));
}
__device__ __forceinline__ void mma16816(float c[4], const uint32_t a[4], uint32_t b0, uint32_t b1) {
    asm volatile("mma.sync.aligned.m16n8k16.row.col.f32.f16.f16.f32 "
        "{%0,%1,%2,%3}, {%4,%5,%6,%7}, {%8,%9}, {%0,%1,%2,%3};"
        : "+f"(c[0]), "+f"(c[1]), "+f"(c[2]), "+f"(c[3])
        : "r"(a[0]), "r"(a[1]), "r"(a[2]), "r"(a[3]), "r"(b0), "r"(b1));
}

// which: 0 = q -> g_qh (hi only), 1 = k -> g_kh/g_kl (hi/lo), 2 = v -> g_vh (hi only)
__global__ void cvt_kernel(const float4* __restrict__ src, int which) {
    int i = blockIdx.x * 256 + threadIdx.x;
    float4 v = src[i];
    __half h0 = __float2half_rn(v.x), h1 = __float2half_rn(v.y);
    __half h2 = __float2half_rn(v.z), h3 = __float2half_rn(v.w);
    uint2 hw = make_uint2(
        (uint32_t)__half_as_ushort(h0) | ((uint32_t)__half_as_ushort(h1) << 16),
        (uint32_t)__half_as_ushort(h2) | ((uint32_t)__half_as_ushort(h3) << 16));
    if (which == 0) {
        reinterpret_cast<uint2*>(g_qh)[i] = hw;
    } else if (which == 2) {
        reinterpret_cast<uint2*>(g_vh)[i] = hw;
    } else {
        reinterpret_cast<uint2*>(g_kh)[i] = hw;
        __half l0 = __float2half_rn(v.x - __half2float(h0));
        __half l1 = __float2half_rn(v.y - __half2float(h1));
        __half l2 = __float2half_rn(v.z - __half2float(h2));
        __half l3 = __float2half_rn(v.w - __half2float(h3));
        reinterpret_cast<uint2*>(g_kl)[i] = make_uint2(
            (uint32_t)__half_as_ushort(l0) | ((uint32_t)__half_as_ushort(l1) << 16),
            (uint32_t)__half_as_ushort(l2) | ((uint32_t)__half_as_ushort(l3) << 16));
    }
}

// load one 64-row kv chunk (Kh,Kl,Vh) into buffer buf
__device__ __forceinline__ void load_kv_chunk(uint32_t sb, int buf, int bh, int ch, int tid) {
    uint32_t base = sb + SKV + (uint32_t)buf * KVS;
    size_t eo = ((size_t)bh * 2048 + (size_t)ch * CK) * 128;
    const char* kh = (const char*)(g_kh + eo);
    const char* kl = (const char*)(g_kl + eo);
    const char* vh = (const char*)(g_vh + eo);
    #pragma unroll
    for (int ii = 0; ii < 4; ii++) {
        int i = tid + ii * 256;
        uint32_t r = (uint32_t)(i >> 4), c = (uint32_t)(i & 15);
        uint32_t dst = SWA(0, r, c);
        const size_t so = (size_t)r * 256 + c * 16;
        cp16(base + OKH + dst, kh + so);
        cp16(base + OKL + dst, kl + so);
        cp16(base + OVH + dst, vh + so);
    }
}

__global__ __launch_bounds__(256, 1) void attn_main(const float* __restrict__ scale_p,
                                                    float* __restrict__ out) {
    extern __shared__ __align__(1024) char smem[];
    uint32_t sb = smem_u32(smem);
    const int tid = threadIdx.x;
    const int warp = tid >> 5, lane = tid & 31;
    const int bh = blockIdx.x >> 4, qt = blockIdx.x & 15;

    // ---- prologue: Q hi tile (128 rows x 256B) + chunk 0 ----
    {
        size_t eo = ((size_t)bh * 2048 + (size_t)qt * 128) * 128;
        const char* qh = (const char*)(g_qh + eo);
        #pragma unroll
        for (int ii = 0; ii < 8; ii++) {
            int i = tid + ii * 256;
            uint32_t r = (uint32_t)(i >> 4), c = (uint32_t)(i & 15);
            cp16(sb + SQH + SWA(0, r, c), qh + (size_t)r * 256 + c * 16);
        }
    }
    load_kv_chunk(sb, 0, bh, 0, tid);
    CPASYNC_COMMIT();

    const float scale = __ldg(scale_p);

    const uint32_t rowA  = (uint32_t)(16 * warp + (lane & 15));
    const uint32_t colA  = (uint32_t)(lane >> 4);
    const uint32_t rowKb = (uint32_t)((lane & 7) + ((lane >> 4) << 3));
    const uint32_t colKb = (uint32_t)((lane >> 3) & 1);
    const uint32_t rowVb = (uint32_t)((lane & 7) + (((lane >> 3) & 1) << 3));
    const uint32_t colVb = (uint32_t)(lane >> 4);

    float o[16][4];
    #pragma unroll
    for (int j = 0; j < 16; j++) { o[j][0] = o[j][1] = o[j][2] = o[j][3] = 0.f; }

    // wait for Q + chunk0; preload Q fragments once (iteration-invariant)
    CPASYNC_WAIT0();
    __syncthreads();
    uint32_t qf[8][4];
    #pragma unroll
    for (int kc = 0; kc < 8; kc++)
        ldsm4(qf[kc], SWA(sb + SQH, rowA, 2 * kc + colA));

    for (int it = 0; it < N_ITER; ++it) {
        if (it > 0) {
            CPASYNC_WAIT0();      // wait chunk it
            __syncthreads();      // all warps done with buffer (it+1)&1 from iter it-1
        }
        if (it + 1 < N_ITER) { load_kv_chunk(sb, (it + 1) & 1, bh, it + 1, tid); }
        CPASYNC_COMMIT();

        const uint32_t kb = sb + SKV + (uint32_t)(it & 1) * KVS;

        // ---- gemm1: S[16x64] = Qh*Kh' + Qh*Kl' ----
        float s[8][4];
        #pragma unroll
        for (int j = 0; j < 8; j++) { s[j][0] = s[j][1] = s[j][2] = s[j][3] = 0.f; }

        #pragma unroll
        for (int kc = 0; kc < 8; kc++) {
            uint32_t bH[4][4], bL[4][4];
            #pragma unroll
            for (int ng = 0; ng < 4; ng++) {
                ldsm4(bH[ng], SWA(kb + OKH, 16 * ng + rowKb, 2 * kc + colKb));
                ldsm4(bL[ng], SWA(kb + OKL, 16 * ng + rowKb, 2 * kc + colKb));
            }
            #pragma unroll
            for (int ng = 0; ng < 4; ng++) {
                mma16816(s[2*ng],   qf[kc], bH[ng][0], bH[ng][1]);
                mma16816(s[2*ng+1], qf[kc], bH[ng][2], bH[ng][3]);
            }
            #pragma unroll
            for (int ng = 0; ng < 4; ng++) {
                mma16816(s[2*ng],   qf[kc], bL[ng][0], bL[ng][1]);
                mma16816(s[2*ng+1], qf[kc], bL[ng][2], bL[ng][3]);
            }
        }

        // ---- P = relu(S*scale)^2, packed straight to fp16 A-frags ----
        // pf[kc][q]: A fragment registers for gemm2 (single fp16 precision)
        uint32_t pf[4][4];
        #pragma unroll
        for (int kc = 0; kc < 4; kc++)
            #pragma unroll
            for (int q = 0; q < 4; q++) {
                const int tile = 2 * kc + (q >> 1);
                const int e0 = (q & 1) * 2;
                float x0 = fmaxf(s[tile][e0]     * scale, 0.f);
                float x1 = fmaxf(s[tile][e0 + 1] * scale, 0.f);
                __half2 h2 = __floats2half2_rn(x0 * x0, x1 * x1);
                pf[kc][q] = *reinterpret_cast<uint32_t*>(&h2);
            }

        // ---- gemm2: O[16x128] += P * Vh  (single-term) ----
        #pragma unroll
        for (int kc = 0; kc < 4; kc++) {
            uint32_t vf[8][4];
            #pragma unroll
            for (int dg = 0; dg < 8; dg++)
                ldsm4t(vf[dg], SWA(kb + OVH, 16 * kc + rowVb, 2 * dg + colVb));
            #pragma unroll
            for (int dg = 0; dg < 8; dg++) {
                mma16816(o[2*dg],   pf[kc], vf[dg][0], vf[dg][1]);
                mma16816(o[2*dg+1], pf[kc], vf[dg][2], vf[dg][3]);
            }
        }
    }

    // ---- writeout ----
    {
        const int g = lane >> 2, t = lane & 3;
        size_t row0 = (size_t)bh * 2048 + (size_t)qt * 128 + 16 * warp + g;
        float* r0 = out + row0 * 128 + 2 * t;
        float* r1 = r0 + 8 * 128;
        #pragma unroll
        for (int j = 0; j < 16; j++) {
            *reinterpret_cast<float2*>(r0 + 8 * j) = make_float2(o[j][0], o[j][1]);
            *reinterpret_cast<float2*>(r1 + 8 * j) = make_float2(o[j][2], o[j][3]);
        }
    }
}

extern "C" void kernel_launch(void* const* d_in, const int* in_sizes, int n_in,
                              void* d_out, int out_size) {
    const float* q     = (const float*)d_in[0];
    const float* k     = (const float*)d_in[1];
    const float* v     = (const float*)d_in[2];
    const float* scale = (const float*)d_in[3];
    float* out = (float*)d_out;

    cudaFuncSetAttribute(attn_main, cudaFuncAttributeMaxDynamicSharedMemorySize, SMEM_TOTAL);

    cvt_kernel<<<8192, 256>>>((const float4*)q, 0);
    cvt_kernel<<<8192, 256>>>((const float4*)k, 1);
    cvt_kernel<<<8192, 256>>>((const float4*)v, 2);
    attn_main<<<512, 256, SMEM_TOTAL>>>(scale, out);
}